// round 15
// baseline (speedup 1.0000x reference)
#include <cuda_runtime.h>
#include <cstdint>

// TaylorMap via classic mma.sync m16n8k16 f16/f32 (sm_103: no tcgen05).
//   out = x + P(x) @ W,  P:[B,969->992] monomials (reference order) in f16.
// R15 = R14 (53.1us, rel_err 1.1e-4) with per-warp staging halved (two 2KB
// buffers, 32-k chunks, 64B rows + 4-unit XOR swizzle) so smem drops to
// 64.5KB -> 3 CTAs/SM (24 warps vs 16). Bytes through L1 unchanged; the win
// is L1 duty cycle (75.8% -> ~90%). Reg cap 84 via launch_bounds(256,3).

typedef unsigned int u32;
typedef unsigned long long u64;

#define NF 16
#define KTOT 992
#define NSTEP 62
#define BLOCK 256
#define GRID 444                    // 3 CTAs/SM
#define NBATCH 262144
#define NTILES (NBATCH / 32)        // 8192 tiles of 32 rows
#define BFRAG_BYTES (NSTEP * 32 * 16)     // 31744
#define PSM_OFF BFRAG_BYTES
#define PSM_PER_WARP 4096           // two 2KB chunk buffers (32 rows x 64B)
#define SMEM_TOTAL (BFRAG_BYTES + 8 * PSM_PER_WARP)   // 64512

#define ROW3(i, a, b) (153 + ((i) * ((i) + 1) * ((i) + 2)) / 6 \
                       + ((a) * ((a) + 1)) / 2 + (b))

__device__ unsigned int g_ticket;
__global__ void reset_ticket_kernel() { g_ticket = 0u; }

__device__ __forceinline__ u32 smem_u32(const void* p) {
    u32 a;
    asm("{ .reg .u64 t; cvta.to.shared.u64 t, %1; cvt.u32.u64 %0, t; }"
        : "=r"(a) : "l"(p));
    return a;
}
__device__ __forceinline__ u32 packf16(float hi, float lo) {
    u32 r; asm("cvt.rn.f16x2.f32 %0, %1, %2;" : "=r"(r) : "f"(hi), "f"(lo));
    return r;
}

// ---- tiny integer-sequence machinery (no std headers) ----
template <int... Is> struct ISeq {};
template <int N, int... Is> struct MkSeq : MkSeq<N - 1, N - 1, Is...> {};
template <int... Is> struct MkSeq<0, Is...> { using T = ISeq<Is...>; };

__host__ __device__ constexpr int pair_a(int p) {
    int a = 0;
    while ((a + 1) * (a + 2) / 2 <= p) a++;
    return a;
}

// ---- shared context parameter pack ----
#define CTX_DECL float (&xs)[16], float& pend,                                 \
    u32& s0, u32& s1, u32& s2, u32& s3,                                        \
    const u32 sa0, const u32 sa1, const u32 sa2, const u32 sa3,                \
    const u32 rsu0, const u32 rsu1,                                            \
    const u32 x0, const u32 x1, const u32 rb,                                  \
    float& d00, float& d01, float& d02, float& d03,                            \
    float& d10, float& d11, float& d12, float& d13,                            \
    float& d20, float& d21, float& d22, float& d23,                            \
    float& d30, float& d31, float& d32, float& d33
#define CTX_ARGS xs, pend, s0, s1, s2, s3, sa0, sa1, sa2, sa3,                 \
    rsu0, rsu1, x0, x1, rb,                                                    \
    d00, d01, d02, d03, d10, d11, d12, d13, d20, d21, d22, d23, d30, d31, d32, d33

// One consume k-step (chunk CH of 2 ksteps, step S in 0..1):
// 1 B LDS.128 + 2 ldmatrix.x4 + 4 mma. Buffer parity = CH & 1.
template <int CH, int S>
__device__ __forceinline__ void cstep(CTX_DECL) {
    constexpr u32 PAR = (u32)((CH & 1) * 2048);
    u32 xoff = (S == 0) ? x0 : x1;
    u32 b0, b1, b2, b3;
    asm volatile("ld.shared.v4.b32 {%0,%1,%2,%3}, [%4];"
        : "=r"(b0), "=r"(b1), "=r"(b2), "=r"(b3)
        : "r"(rb + (u32)((2 * CH + S) * 512)));
    u32 a0, a1, a2, a3;
    asm volatile("ldmatrix.sync.aligned.m8n8.x4.shared.b16 "
        "{%0,%1,%2,%3}, [%4];"
        : "=r"(a0), "=r"(a1), "=r"(a2), "=r"(a3)
        : "r"(rsu0 + PAR + xoff));
    asm volatile("mma.sync.aligned.m16n8k16.row.col.f32.f16.f16.f32 "
        "{%0,%1,%2,%3}, {%4,%5,%6,%7}, {%8,%9}, {%0,%1,%2,%3};"
        : "+f"(d00), "+f"(d01), "+f"(d02), "+f"(d03)
        : "r"(a0), "r"(a1), "r"(a2), "r"(a3), "r"(b0), "r"(b1));
    asm volatile("mma.sync.aligned.m16n8k16.row.col.f32.f16.f16.f32 "
        "{%0,%1,%2,%3}, {%4,%5,%6,%7}, {%8,%9}, {%0,%1,%2,%3};"
        : "+f"(d10), "+f"(d11), "+f"(d12), "+f"(d13)
        : "r"(a0), "r"(a1), "r"(a2), "r"(a3), "r"(b2), "r"(b3));
    u32 c0, c1, c2, c3;
    asm volatile("ldmatrix.sync.aligned.m8n8.x4.shared.b16 "
        "{%0,%1,%2,%3}, [%4];"
        : "=r"(c0), "=r"(c1), "=r"(c2), "=r"(c3)
        : "r"(rsu1 + PAR + xoff));
    asm volatile("mma.sync.aligned.m16n8k16.row.col.f32.f16.f16.f32 "
        "{%0,%1,%2,%3}, {%4,%5,%6,%7}, {%8,%9}, {%0,%1,%2,%3};"
        : "+f"(d20), "+f"(d21), "+f"(d22), "+f"(d23)
        : "r"(c0), "r"(c1), "r"(c2), "r"(c3), "r"(b0), "r"(b1));
    asm volatile("mma.sync.aligned.m16n8k16.row.col.f32.f16.f16.f32 "
        "{%0,%1,%2,%3}, {%4,%5,%6,%7}, {%8,%9}, {%0,%1,%2,%3};"
        : "+f"(d30), "+f"(d31), "+f"(d32), "+f"(d33)
        : "r"(c0), "r"(c1), "r"(c2), "r"(c3), "r"(b2), "r"(b3));
}

// Emit monomial KK (STRICTLY ASCENDING KK): pack f16 pairs into s0..s3,
// STS.128 every 8 k, interleave one consume step of the previous 32-k chunk
// every 16 k, syncwarp at each 32-k chunk end.
template <int KK>
__device__ __forceinline__ void emitk(float v, CTX_DECL) {
    if constexpr ((KK & 1) == 0) {
        pend = v;
    } else {
        u32 h = packf16(v, pend);
        constexpr int kp = KK >> 1;
        constexpr int sel = kp & 3;
        if constexpr (sel == 0) s0 = h;
        else if constexpr (sel == 1) s1 = h;
        else if constexpr (sel == 2) s2 = h;
        else {
            s3 = h;
            constexpr int j = kp >> 2;               // global 16B unit 0..123
            constexpr int ju = j & 3;                // unit within chunk
            constexpr u32 PAR = (u32)(((j >> 2) & 1) * 2048);
            u32 base = (ju == 0) ? sa0 : (ju == 1) ? sa1
                     : (ju == 2) ? sa2 : sa3;
            asm volatile("st.shared.v4.b32 [%0], {%1,%2,%3,%4};"
                :: "r"(base + PAR), "r"(s0), "r"(s1), "r"(s2), "r"(s3));
        }
        if constexpr (KK >= 47 && (KK & 15) == 15) {
            cstep<(KK >> 5) - 1, (KK >> 4) & 1>(CTX_ARGS);
        }
        if constexpr ((KK & 31) == 31) { __syncwarp(); }
    }
}

// ---- ascending-k traversal (validated in R13/R14) ----
template <int... Is>
__device__ __forceinline__ void do_deg1(ISeq<Is...>, CTX_DECL) {
    (emitk<1 + Is>(xs[Is], CTX_ARGS), ...);
}
template <int P>
__device__ __forceinline__ void do_p2(CTX_DECL) {
    constexpr int A = pair_a(P);
    constexpr int B = P - A * (A + 1) / 2;
    emitk<17 + P>(xs[A] * xs[B], CTX_ARGS);
}
template <int... Ps>
__device__ __forceinline__ void do_deg2(ISeq<Ps...>, CTX_DECL) {
    (do_p2<Ps>(CTX_ARGS), ...);
}
template <int II, int A, int... Bs>
__device__ __forceinline__ void emit3run(float tp, ISeq<Bs...>, CTX_DECL) {
    (emitk<ROW3(II, A, Bs)>(tp * xs[Bs], CTX_ARGS), ...);
}
template <int II, int... As>
__device__ __forceinline__ void do_ii(ISeq<As...>, CTX_DECL) {
    (emit3run<II, As>(xs[II] * xs[As], typename MkSeq<As + 1>::T{}, CTX_ARGS), ...);
}
template <int... IIs>
__device__ __forceinline__ void do_deg3(ISeq<IIs...>, CTX_DECL) {
    (do_ii<IIs>(typename MkSeq<IIs + 1>::T{}, CTX_ARGS), ...);
}
template <int... Js>
__device__ __forceinline__ void do_pad(ISeq<Js...>, CTX_DECL) {
    (emitk<969 + Js>(0.0f, CTX_ARGS), ...);
}

__global__ void __launch_bounds__(BLOCK, 3)
taylor_mma(const float* __restrict__ x, const float* __restrict__ W,
           float* __restrict__ out)
{
    extern __shared__ unsigned char smem[];
    const u32 sbase = smem_u32(smem);
    const int tid = threadIdx.x;
    const int warp = tid >> 5;
    const int lane = tid & 31;
    const int g = lane >> 2;          // fragment row group 0..7
    const int t = lane & 3;           // thread-in-group 0..3

    // ---- build B fragments once (validated R7/R8/R13/R14) ----
#pragma unroll 1
    for (int e = tid; e < NSTEP * 32; e += BLOCK) {
        int s = e >> 5, l = e & 31;
        int lg = l >> 2, lt = l & 3;
        int k1 = 16 * s + 2 * lt;
#define WGET(K, C) (((K) < 969) ? W[(K) * NF + (C)] : 0.0f)
        uint4 v;
        v.x = packf16(WGET(k1 + 1, lg),     WGET(k1, lg));
        v.y = packf16(WGET(k1 + 9, lg),     WGET(k1 + 8, lg));
        v.z = packf16(WGET(k1 + 1, lg + 8), WGET(k1, lg + 8));
        v.w = packf16(WGET(k1 + 9, lg + 8), WGET(k1 + 8, lg + 8));
#undef WGET
        *reinterpret_cast<uint4*>(smem + e * 16) = v;
    }
    __syncthreads();

    // ---- stage addressing: 64B rows, unit swizzle phys=(u^((row>>1)&3))*16
    const u32 stg = sbase + PSM_OFF + warp * PSM_PER_WARP;   // buf0; buf1=+2048
    const u32 zr = ((u32)lane >> 1) & 3;
    const u32 rowb = stg + (u32)lane * 64;
    const u32 sa0 = rowb + ((0u ^ zr) << 4);
    const u32 sa1 = rowb + ((1u ^ zr) << 4);
    const u32 sa2 = rowb + ((2u ^ zr) << 4);
    const u32 sa3 = rowb + ((3u ^ zr) << 4);
    // consumer: su0 rows 0..15, su1 rows 16..31 (same swizzle phase)
    const u32 rsu0 = stg + (u32)(lane & 15) * 64;
    const u32 rsu1 = rsu0 + 1024;
    const u32 z2 = (((u32)lane & 15) >> 1) & 3;
    const u32 lu = (u32)lane >> 4;
    const u32 x0 = ((0u + lu) ^ z2) << 4;
    const u32 x1 = ((2u + lu) ^ z2) << 4;
    const u32 rb = sbase + lane * 16;    // B fragment base

    for (;;) {
        u32 tk;
        if (lane == 0) tk = atomicAdd(&g_ticket, 1u);
        tk = __shfl_sync(0xffffffffu, tk, 0);
        if (tk >= NTILES) break;

        const long long base = (long long)tk * 32;

        const float4* xv = reinterpret_cast<const float4*>(x + (base + lane) * NF);
        float4 v0 = xv[0], v1 = xv[1], v2 = xv[2], v3 = xv[3];
        float xs[NF] = { v0.x, v0.y, v0.z, v0.w,  v1.x, v1.y, v1.z, v1.w,
                         v2.x, v2.y, v2.z, v2.w,  v3.x, v3.y, v3.z, v3.w };

        float d00 = 0, d01 = 0, d02 = 0, d03 = 0;   // su0,nt0
        float d10 = 0, d11 = 0, d12 = 0, d13 = 0;   // su0,nt1
        float d20 = 0, d21 = 0, d22 = 0, d23 = 0;   // su1,nt0
        float d30 = 0, d31 = 0, d32 = 0, d33 = 0;   // su1,nt1
        float pend = 0.0f;
        u32 s0 = 0, s1 = 0, s2 = 0, s3 = 0;

        // ---- fully-expanded generation, ascending k = 0..991 ----
        emitk<0>(1.0f, CTX_ARGS);
        do_deg1(typename MkSeq<16>::T{}, CTX_ARGS);
        do_deg2(typename MkSeq<136>::T{}, CTX_ARGS);
        do_deg3(typename MkSeq<16>::T{}, CTX_ARGS);
        do_pad(typename MkSeq<KTOT - 969>::T{}, CTX_ARGS);

        // tail consume steps (chunk 30 = ksteps 60,61)
        cstep<30, 0>(CTX_ARGS);
        cstep<30, 1>(CTX_ARGS);

        // ---- epilogue: out = x + D (f32; x path exact) ----
#define EPI(D0, D1, D2, D3, SU, NT) do {                                       \
        long long rlo = base + (SU) * 16 + g;                                  \
        int c = (NT) * 8 + 2 * t;                                              \
        const float2 xlo = *reinterpret_cast<const float2*>(x + rlo * NF + c); \
        float2 olo; olo.x = xlo.x + (D0); olo.y = xlo.y + (D1);                \
        *reinterpret_cast<float2*>(out + rlo * NF + c) = olo;                  \
        const float2 xhi = *reinterpret_cast<const float2*>(x + (rlo + 8) * NF + c); \
        float2 ohi; ohi.x = xhi.x + (D2); ohi.y = xhi.y + (D3);                \
        *reinterpret_cast<float2*>(out + (rlo + 8) * NF + c) = ohi;            \
    } while (0)
        EPI(d00, d01, d02, d03, 0, 0);
        EPI(d10, d11, d12, d13, 0, 1);
        EPI(d20, d21, d22, d23, 1, 0);
        EPI(d30, d31, d32, d33, 1, 1);
#undef EPI
    }
}

extern "C" void kernel_launch(void* const* d_in, const int* in_sizes, int n_in,
                              void* d_out, int out_size)
{
    const float* x = (const float*)d_in[0];   // [262144, 16]
    const float* W = (const float*)d_in[1];   // [969, 16]
    float* out = (float*)d_out;

    cudaFuncSetAttribute(taylor_mma,
                         cudaFuncAttributeMaxDynamicSharedMemorySize,
                         SMEM_TOTAL);

    reset_ticket_kernel<<<1, 1>>>();
    taylor_mma<<<GRID, BLOCK, SMEM_TOTAL>>>(x, W, out);
}

// round 16
// speedup vs baseline: 1.1113x; 1.1113x over previous
#include <cuda_runtime.h>
#include <cstdint>

// TaylorMap via classic mma.sync m16n8k16 f16/f32 (sm_103: no tcgen05).
//   out = x + P(x) @ W,  P:[B,969->992] monomials (reference order) in f16.
// R16 = R14 (53.1us, rel_err 1.1e-4; 2 CTAs/SM, 128 regs, 8KB/warp stage)
// with each consume k-step SPLIT: PRE (B LDS.128 + 2 ldmatrix.x4 into named
// regs) at KK%16==7, MMA (4 mma) at KK%16==15 — an 8-k software pipeline that
// hides the ldmatrix->mma latency that capped L1 duty at 76%.

typedef unsigned int u32;
typedef unsigned long long u64;

#define NF 16
#define KTOT 992
#define NSTEP 62
#define BLOCK 256
#define GRID 296                    // 2 CTAs/SM
#define NBATCH 262144
#define NTILES (NBATCH / 32)        // 8192 tiles of 32 rows
#define BFRAG_BYTES (NSTEP * 32 * 16)     // 31744
#define PSM_OFF BFRAG_BYTES
#define PSM_PER_WARP 8192           // two 4KB chunk buffers (32 rows x 128B)
#define SMEM_TOTAL (BFRAG_BYTES + 8 * PSM_PER_WARP)   // 97280

#define ROW3(i, a, b) (153 + ((i) * ((i) + 1) * ((i) + 2)) / 6 \
                       + ((a) * ((a) + 1)) / 2 + (b))

__device__ unsigned int g_ticket;
__global__ void reset_ticket_kernel() { g_ticket = 0u; }

__device__ __forceinline__ u32 smem_u32(const void* p) {
    u32 a;
    asm("{ .reg .u64 t; cvta.to.shared.u64 t, %1; cvt.u32.u64 %0, t; }"
        : "=r"(a) : "l"(p));
    return a;
}
__device__ __forceinline__ u32 packf16(float hi, float lo) {
    u32 r; asm("cvt.rn.f16x2.f32 %0, %1, %2;" : "=r"(r) : "f"(hi), "f"(lo));
    return r;
}

// ---- tiny integer-sequence machinery (no std headers) ----
template <int... Is> struct ISeq {};
template <int N, int... Is> struct MkSeq : MkSeq<N - 1, N - 1, Is...> {};
template <int... Is> struct MkSeq<0, Is...> { using T = ISeq<Is...>; };

__host__ __device__ constexpr int pair_a(int p) {
    int a = 0;
    while ((a + 1) * (a + 2) / 2 <= p) a++;
    return a;
}

// ---- shared context parameter pack ----
#define CTX_DECL float (&xs)[16], float& pend,                                 \
    u32& s0, u32& s1, u32& s2, u32& s3,                                        \
    u32& pa0, u32& pa1, u32& pa2, u32& pa3,                                    \
    u32& pc0, u32& pc1, u32& pc2, u32& pc3,                                    \
    u32& pb0, u32& pb1, u32& pb2, u32& pb3,                                    \
    const u32 sa0, const u32 sa1, const u32 sa2, const u32 sa3,                \
    const u32 sa4, const u32 sa5, const u32 sa6, const u32 sa7,                \
    const u32 rsu0, const u32 rsu1,                                            \
    const u32 x0, const u32 x1, const u32 x2, const u32 x3, const u32 rb,      \
    float& d00, float& d01, float& d02, float& d03,                            \
    float& d10, float& d11, float& d12, float& d13,                            \
    float& d20, float& d21, float& d22, float& d23,                            \
    float& d30, float& d31, float& d32, float& d33
#define CTX_ARGS xs, pend, s0, s1, s2, s3,                                     \
    pa0, pa1, pa2, pa3, pc0, pc1, pc2, pc3, pb0, pb1, pb2, pb3,                \
    sa0, sa1, sa2, sa3, sa4, sa5, sa6, sa7, rsu0, rsu1,                        \
    x0, x1, x2, x3, rb,                                                        \
    d00, d01, d02, d03, d10, d11, d12, d13, d20, d21, d22, d23, d30, d31, d32, d33

// PRE half of a consume k-step: B LDS.128 + 2 ldmatrix.x4 into named regs.
template <int CH, int S>
__device__ __forceinline__ void pstep(CTX_DECL) {
    constexpr u32 PAR = (u32)((CH & 1) * 4096);
    u32 xoff = (S == 0) ? x0 : (S == 1) ? x1 : (S == 2) ? x2 : x3;
    asm volatile("ld.shared.v4.b32 {%0,%1,%2,%3}, [%4];"
        : "=r"(pb0), "=r"(pb1), "=r"(pb2), "=r"(pb3)
        : "r"(rb + (u32)((4 * CH + S) * 512)));
    asm volatile("ldmatrix.sync.aligned.m8n8.x4.shared.b16 "
        "{%0,%1,%2,%3}, [%4];"
        : "=r"(pa0), "=r"(pa1), "=r"(pa2), "=r"(pa3)
        : "r"(rsu0 + PAR + xoff));
    asm volatile("ldmatrix.sync.aligned.m8n8.x4.shared.b16 "
        "{%0,%1,%2,%3}, [%4];"
        : "=r"(pc0), "=r"(pc1), "=r"(pc2), "=r"(pc3)
        : "r"(rsu1 + PAR + xoff));
}

// MMA half: consumes the prefetched regs (no addresses needed).
__device__ __forceinline__ void mstep(CTX_DECL) {
    asm volatile("mma.sync.aligned.m16n8k16.row.col.f32.f16.f16.f32 "
        "{%0,%1,%2,%3}, {%4,%5,%6,%7}, {%8,%9}, {%0,%1,%2,%3};"
        : "+f"(d00), "+f"(d01), "+f"(d02), "+f"(d03)
        : "r"(pa0), "r"(pa1), "r"(pa2), "r"(pa3), "r"(pb0), "r"(pb1));
    asm volatile("mma.sync.aligned.m16n8k16.row.col.f32.f16.f16.f32 "
        "{%0,%1,%2,%3}, {%4,%5,%6,%7}, {%8,%9}, {%0,%1,%2,%3};"
        : "+f"(d10), "+f"(d11), "+f"(d12), "+f"(d13)
        : "r"(pa0), "r"(pa1), "r"(pa2), "r"(pa3), "r"(pb2), "r"(pb3));
    asm volatile("mma.sync.aligned.m16n8k16.row.col.f32.f16.f16.f32 "
        "{%0,%1,%2,%3}, {%4,%5,%6,%7}, {%8,%9}, {%0,%1,%2,%3};"
        : "+f"(d20), "+f"(d21), "+f"(d22), "+f"(d23)
        : "r"(pc0), "r"(pc1), "r"(pc2), "r"(pc3), "r"(pb0), "r"(pb1));
    asm volatile("mma.sync.aligned.m16n8k16.row.col.f32.f16.f16.f32 "
        "{%0,%1,%2,%3}, {%4,%5,%6,%7}, {%8,%9}, {%0,%1,%2,%3};"
        : "+f"(d30), "+f"(d31), "+f"(d32), "+f"(d33)
        : "r"(pc0), "r"(pc1), "r"(pc2), "r"(pc3), "r"(pb2), "r"(pb3));
}

// Emit monomial KK (STRICTLY ASCENDING KK): pack f16 pairs into s0..s3,
// STS.128 every 8 k; PRE for step (CH,S) at KK%16==7, its MMA at KK%16==15
// (8-k pipeline); syncwarp at each 64-k chunk end.
template <int KK>
__device__ __forceinline__ void emitk(float v, CTX_DECL) {
    if constexpr ((KK & 1) == 0) {
        pend = v;
    } else {
        u32 h = packf16(v, pend);
        constexpr int kp = KK >> 1;
        constexpr int sel = kp & 3;
        if constexpr (sel == 0) s0 = h;
        else if constexpr (sel == 1) s1 = h;
        else if constexpr (sel == 2) s2 = h;
        else {
            s3 = h;
            constexpr int j = kp >> 2;               // global 16B unit 0..123
            constexpr int j7 = j & 7;
            constexpr u32 PAR = (u32)(((j >> 3) & 1) * 4096);
            u32 base = (j7 == 0) ? sa0 : (j7 == 1) ? sa1 : (j7 == 2) ? sa2
                     : (j7 == 3) ? sa3 : (j7 == 4) ? sa4 : (j7 == 5) ? sa5
                     : (j7 == 6) ? sa6 : sa7;
            asm volatile("st.shared.v4.b32 [%0], {%1,%2,%3,%4};"
                :: "r"(base + PAR), "r"(s0), "r"(s1), "r"(s2), "r"(s3));
        }
        if constexpr (KK >= 71 && (KK & 15) == 7) {
            pstep<((KK + 8) >> 6) - 1, ((KK + 8) >> 4) & 3>(CTX_ARGS);
        }
        if constexpr (KK >= 79 && (KK & 15) == 15) {
            mstep(CTX_ARGS);
        }
        if constexpr ((KK & 63) == 63) { __syncwarp(); }
    }
}

// ---- ascending-k traversal (validated in R13/R14) ----
template <int... Is>
__device__ __forceinline__ void do_deg1(ISeq<Is...>, CTX_DECL) {
    (emitk<1 + Is>(xs[Is], CTX_ARGS), ...);
}
template <int P>
__device__ __forceinline__ void do_p2(CTX_DECL) {
    constexpr int A = pair_a(P);
    constexpr int B = P - A * (A + 1) / 2;
    emitk<17 + P>(xs[A] * xs[B], CTX_ARGS);
}
template <int... Ps>
__device__ __forceinline__ void do_deg2(ISeq<Ps...>, CTX_DECL) {
    (do_p2<Ps>(CTX_ARGS), ...);
}
template <int II, int A, int... Bs>
__device__ __forceinline__ void emit3run(float tp, ISeq<Bs...>, CTX_DECL) {
    (emitk<ROW3(II, A, Bs)>(tp * xs[Bs], CTX_ARGS), ...);
}
template <int II, int... As>
__device__ __forceinline__ void do_ii(ISeq<As...>, CTX_DECL) {
    (emit3run<II, As>(xs[II] * xs[As], typename MkSeq<As + 1>::T{}, CTX_ARGS), ...);
}
template <int... IIs>
__device__ __forceinline__ void do_deg3(ISeq<IIs...>, CTX_DECL) {
    (do_ii<IIs>(typename MkSeq<IIs + 1>::T{}, CTX_ARGS), ...);
}
template <int... Js>
__device__ __forceinline__ void do_pad(ISeq<Js...>, CTX_DECL) {
    (emitk<969 + Js>(0.0f, CTX_ARGS), ...);
}

__global__ void __launch_bounds__(BLOCK, 2)
taylor_mma(const float* __restrict__ x, const float* __restrict__ W,
           float* __restrict__ out)
{
    extern __shared__ unsigned char smem[];
    const u32 sbase = smem_u32(smem);
    const int tid = threadIdx.x;
    const int warp = tid >> 5;
    const int lane = tid & 31;
    const int g = lane >> 2;          // fragment row group 0..7
    const int t = lane & 3;           // thread-in-group 0..3

    // ---- build B fragments once (validated R7/R8/R13/R14) ----
#pragma unroll 1
    for (int e = tid; e < NSTEP * 32; e += BLOCK) {
        int s = e >> 5, l = e & 31;
        int lg = l >> 2, lt = l & 3;
        int k1 = 16 * s + 2 * lt;
#define WGET(K, C) (((K) < 969) ? W[(K) * NF + (C)] : 0.0f)
        uint4 v;
        v.x = packf16(WGET(k1 + 1, lg),     WGET(k1, lg));
        v.y = packf16(WGET(k1 + 9, lg),     WGET(k1 + 8, lg));
        v.z = packf16(WGET(k1 + 1, lg + 8), WGET(k1, lg + 8));
        v.w = packf16(WGET(k1 + 9, lg + 8), WGET(k1 + 8, lg + 8));
#undef WGET
        *reinterpret_cast<uint4*>(smem + e * 16) = v;
    }
    __syncthreads();

    // ---- stage addressing (row-major, unit swizzle phys=(u^(row&7))*16) ----
    const u32 stg = sbase + PSM_OFF + warp * PSM_PER_WARP;   // buf0; buf1=+4096
    const u32 l7 = (u32)(lane & 7);
    const u32 rowb = stg + (u32)lane * 128;
    const u32 sa0 = rowb + ((0u ^ l7) << 4);
    const u32 sa1 = rowb + ((1u ^ l7) << 4);
    const u32 sa2 = rowb + ((2u ^ l7) << 4);
    const u32 sa3 = rowb + ((3u ^ l7) << 4);
    const u32 sa4 = rowb + ((4u ^ l7) << 4);
    const u32 sa5 = rowb + ((5u ^ l7) << 4);
    const u32 sa6 = rowb + ((6u ^ l7) << 4);
    const u32 sa7 = rowb + ((7u ^ l7) << 4);
    // consumer ldmatrix row bases: R = lane&15 (su0 rows 0..15; su1 +16)
    const u32 rsu0 = stg + (u32)(lane & 15) * 128;
    const u32 rsu1 = rsu0 + 2048;
    // per-step unit offsets: x_S = ((2S + lane>>4) ^ (lane&7)) << 4
    const u32 lu = (u32)(lane >> 4);
    const u32 x0 = ((0u + lu) ^ l7) << 4;
    const u32 x1 = ((2u + lu) ^ l7) << 4;
    const u32 x2 = ((4u + lu) ^ l7) << 4;
    const u32 x3 = ((6u + lu) ^ l7) << 4;
    const u32 rb = sbase + lane * 16;    // B fragment base

    for (;;) {
        u32 tk;
        if (lane == 0) tk = atomicAdd(&g_ticket, 1u);
        tk = __shfl_sync(0xffffffffu, tk, 0);
        if (tk >= NTILES) break;

        const long long base = (long long)tk * 32;

        const float4* xv = reinterpret_cast<const float4*>(x + (base + lane) * NF);
        float4 v0 = xv[0], v1 = xv[1], v2 = xv[2], v3 = xv[3];
        float xs[NF] = { v0.x, v0.y, v0.z, v0.w,  v1.x, v1.y, v1.z, v1.w,
                         v2.x, v2.y, v2.z, v2.w,  v3.x, v3.y, v3.z, v3.w };

        float d00 = 0, d01 = 0, d02 = 0, d03 = 0;   // su0,nt0
        float d10 = 0, d11 = 0, d12 = 0, d13 = 0;   // su0,nt1
        float d20 = 0, d21 = 0, d22 = 0, d23 = 0;   // su1,nt0
        float d30 = 0, d31 = 0, d32 = 0, d33 = 0;   // su1,nt1
        float pend = 0.0f;
        u32 s0 = 0, s1 = 0, s2 = 0, s3 = 0;
        u32 pa0 = 0, pa1 = 0, pa2 = 0, pa3 = 0;
        u32 pc0 = 0, pc1 = 0, pc2 = 0, pc3 = 0;
        u32 pb0 = 0, pb1 = 0, pb2 = 0, pb3 = 0;

        // ---- fully-expanded generation, ascending k = 0..991 ----
        emitk<0>(1.0f, CTX_ARGS);
        do_deg1(typename MkSeq<16>::T{}, CTX_ARGS);
        do_deg2(typename MkSeq<136>::T{}, CTX_ARGS);
        do_deg3(typename MkSeq<16>::T{}, CTX_ARGS);
        do_pad(typename MkSeq<KTOT - 969>::T{}, CTX_ARGS);

        // tail: remaining steps (14,2),(14,3),(15,0),(15,1)
        pstep<14, 2>(CTX_ARGS); mstep(CTX_ARGS);
        pstep<14, 3>(CTX_ARGS); mstep(CTX_ARGS);
        pstep<15, 0>(CTX_ARGS); mstep(CTX_ARGS);
        pstep<15, 1>(CTX_ARGS); mstep(CTX_ARGS);

        // ---- epilogue: out = x + D (f32; x path exact) ----
#define EPI(D0, D1, D2, D3, SU, NT) do {                                       \
        long long rlo = base + (SU) * 16 + g;                                  \
        int c = (NT) * 8 + 2 * t;                                              \
        const float2 xlo = *reinterpret_cast<const float2*>(x + rlo * NF + c); \
        float2 olo; olo.x = xlo.x + (D0); olo.y = xlo.y + (D1);                \
        *reinterpret_cast<float2*>(out + rlo * NF + c) = olo;                  \
        const float2 xhi = *reinterpret_cast<const float2*>(x + (rlo + 8) * NF + c); \
        float2 ohi; ohi.x = xhi.x + (D2); ohi.y = xhi.y + (D3);                \
        *reinterpret_cast<float2*>(out + (rlo + 8) * NF + c) = ohi;            \
    } while (0)
        EPI(d00, d01, d02, d03, 0, 0);
        EPI(d10, d11, d12, d13, 0, 1);
        EPI(d20, d21, d22, d23, 1, 0);
        EPI(d30, d31, d32, d33, 1, 1);
#undef EPI
    }
}

extern "C" void kernel_launch(void* const* d_in, const int* in_sizes, int n_in,
                              void* d_out, int out_size)
{
    const float* x = (const float*)d_in[0];   // [262144, 16]
    const float* W = (const float*)d_in[1];   // [969, 16]
    float* out = (float*)d_out;

    cudaFuncSetAttribute(taylor_mma,
                         cudaFuncAttributeMaxDynamicSharedMemorySize,
                         SMEM_TOTAL);

    reset_ticket_kernel<<<1, 1>>>();
    taylor_mma<<<GRID, BLOCK, SMEM_TOTAL>>>(x, W, out);
}

// round 17
// speedup vs baseline: 1.1189x; 1.0068x over previous
#include <cuda_runtime.h>
#include <cstdint>

// TaylorMap via classic mma.sync m16n8k16 f16/f32 (sm_103: no tcgen05).
//   out = x + P(x) @ W,  P:[B,969->976] monomials (reference order) in f16.
// R17 = R16 (52.0us, rel_err 1.1e-4) + two cuts:
//  - ticket software pipeline: next atomicAdd issued early (lane 0), shfl
//    deferred past the epilogue -> ATOMG latency hidden behind tile work;
//  - K pad 992->976 (61 ksteps): 1.6% less STS/ldmatrix/LDS/mma.

typedef unsigned int u32;
typedef unsigned long long u64;

#define NF 16
#define KTOT 976
#define NSTEP 61
#define BLOCK 256
#define GRID 296                    // 2 CTAs/SM
#define NBATCH 262144
#define NTILES (NBATCH / 32)        // 8192 tiles of 32 rows
#define BFRAG_BYTES (NSTEP * 32 * 16)     // 31232
#define PSM_OFF BFRAG_BYTES
#define PSM_PER_WARP 8192           // two 4KB chunk buffers (32 rows x 128B)
#define SMEM_TOTAL (BFRAG_BYTES + 8 * PSM_PER_WARP)   // 96768

#define ROW3(i, a, b) (153 + ((i) * ((i) + 1) * ((i) + 2)) / 6 \
                       + ((a) * ((a) + 1)) / 2 + (b))

__device__ unsigned int g_ticket;
__global__ void reset_ticket_kernel() { g_ticket = 0u; }

__device__ __forceinline__ u32 smem_u32(const void* p) {
    u32 a;
    asm("{ .reg .u64 t; cvta.to.shared.u64 t, %1; cvt.u32.u64 %0, t; }"
        : "=r"(a) : "l"(p));
    return a;
}
__device__ __forceinline__ u32 packf16(float hi, float lo) {
    u32 r; asm("cvt.rn.f16x2.f32 %0, %1, %2;" : "=r"(r) : "f"(hi), "f"(lo));
    return r;
}

// ---- tiny integer-sequence machinery (no std headers) ----
template <int... Is> struct ISeq {};
template <int N, int... Is> struct MkSeq : MkSeq<N - 1, N - 1, Is...> {};
template <int... Is> struct MkSeq<0, Is...> { using T = ISeq<Is...>; };

__host__ __device__ constexpr int pair_a(int p) {
    int a = 0;
    while ((a + 1) * (a + 2) / 2 <= p) a++;
    return a;
}

// ---- shared context parameter pack ----
#define CTX_DECL float (&xs)[16], float& pend,                                 \
    u32& s0, u32& s1, u32& s2, u32& s3,                                        \
    u32& pa0, u32& pa1, u32& pa2, u32& pa3,                                    \
    u32& pc0, u32& pc1, u32& pc2, u32& pc3,                                    \
    u32& pb0, u32& pb1, u32& pb2, u32& pb3,                                    \
    const u32 sa0, const u32 sa1, const u32 sa2, const u32 sa3,                \
    const u32 sa4, const u32 sa5, const u32 sa6, const u32 sa7,                \
    const u32 rsu0, const u32 rsu1,                                            \
    const u32 x0, const u32 x1, const u32 x2, const u32 x3, const u32 rb,      \
    float& d00, float& d01, float& d02, float& d03,                            \
    float& d10, float& d11, float& d12, float& d13,                            \
    float& d20, float& d21, float& d22, float& d23,                            \
    float& d30, float& d31, float& d32, float& d33
#define CTX_ARGS xs, pend, s0, s1, s2, s3,                                     \
    pa0, pa1, pa2, pa3, pc0, pc1, pc2, pc3, pb0, pb1, pb2, pb3,                \
    sa0, sa1, sa2, sa3, sa4, sa5, sa6, sa7, rsu0, rsu1,                        \
    x0, x1, x2, x3, rb,                                                        \
    d00, d01, d02, d03, d10, d11, d12, d13, d20, d21, d22, d23, d30, d31, d32, d33

// PRE half of a consume k-step: B LDS.128 + 2 ldmatrix.x4 into named regs.
template <int CH, int S>
__device__ __forceinline__ void pstep(CTX_DECL) {
    constexpr u32 PAR = (u32)((CH & 1) * 4096);
    u32 xoff = (S == 0) ? x0 : (S == 1) ? x1 : (S == 2) ? x2 : x3;
    asm volatile("ld.shared.v4.b32 {%0,%1,%2,%3}, [%4];"
        : "=r"(pb0), "=r"(pb1), "=r"(pb2), "=r"(pb3)
        : "r"(rb + (u32)((4 * CH + S) * 512)));
    asm volatile("ldmatrix.sync.aligned.m8n8.x4.shared.b16 "
        "{%0,%1,%2,%3}, [%4];"
        : "=r"(pa0), "=r"(pa1), "=r"(pa2), "=r"(pa3)
        : "r"(rsu0 + PAR + xoff));
    asm volatile("ldmatrix.sync.aligned.m8n8.x4.shared.b16 "
        "{%0,%1,%2,%3}, [%4];"
        : "=r"(pc0), "=r"(pc1), "=r"(pc2), "=r"(pc3)
        : "r"(rsu1 + PAR + xoff));
}

// MMA half: consumes the prefetched regs.
__device__ __forceinline__ void mstep(CTX_DECL) {
    asm volatile("mma.sync.aligned.m16n8k16.row.col.f32.f16.f16.f32 "
        "{%0,%1,%2,%3}, {%4,%5,%6,%7}, {%8,%9}, {%0,%1,%2,%3};"
        : "+f"(d00), "+f"(d01), "+f"(d02), "+f"(d03)
        : "r"(pa0), "r"(pa1), "r"(pa2), "r"(pa3), "r"(pb0), "r"(pb1));
    asm volatile("mma.sync.aligned.m16n8k16.row.col.f32.f16.f16.f32 "
        "{%0,%1,%2,%3}, {%4,%5,%6,%7}, {%8,%9}, {%0,%1,%2,%3};"
        : "+f"(d10), "+f"(d11), "+f"(d12), "+f"(d13)
        : "r"(pa0), "r"(pa1), "r"(pa2), "r"(pa3), "r"(pb2), "r"(pb3));
    asm volatile("mma.sync.aligned.m16n8k16.row.col.f32.f16.f16.f32 "
        "{%0,%1,%2,%3}, {%4,%5,%6,%7}, {%8,%9}, {%0,%1,%2,%3};"
        : "+f"(d20), "+f"(d21), "+f"(d22), "+f"(d23)
        : "r"(pc0), "r"(pc1), "r"(pc2), "r"(pc3), "r"(pb0), "r"(pb1));
    asm volatile("mma.sync.aligned.m16n8k16.row.col.f32.f16.f16.f32 "
        "{%0,%1,%2,%3}, {%4,%5,%6,%7}, {%8,%9}, {%0,%1,%2,%3};"
        : "+f"(d30), "+f"(d31), "+f"(d32), "+f"(d33)
        : "r"(pc0), "r"(pc1), "r"(pc2), "r"(pc3), "r"(pb2), "r"(pb3));
}

// Emit monomial KK (STRICTLY ASCENDING KK): pack f16 pairs into s0..s3,
// STS.128 every 8 k; PRE for a k-step at KK%16==7, its MMA at KK%16==15
// (8-k pipeline); syncwarp at each 64-k chunk end.
template <int KK>
__device__ __forceinline__ void emitk(float v, CTX_DECL) {
    if constexpr ((KK & 1) == 0) {
        pend = v;
    } else {
        u32 h = packf16(v, pend);
        constexpr int kp = KK >> 1;
        constexpr int sel = kp & 3;
        if constexpr (sel == 0) s0 = h;
        else if constexpr (sel == 1) s1 = h;
        else if constexpr (sel == 2) s2 = h;
        else {
            s3 = h;
            constexpr int j = kp >> 2;               // global 16B unit 0..121
            constexpr int j7 = j & 7;
            constexpr u32 PAR = (u32)(((j >> 3) & 1) * 4096);
            u32 base = (j7 == 0) ? sa0 : (j7 == 1) ? sa1 : (j7 == 2) ? sa2
                     : (j7 == 3) ? sa3 : (j7 == 4) ? sa4 : (j7 == 5) ? sa5
                     : (j7 == 6) ? sa6 : sa7;
            asm volatile("st.shared.v4.b32 [%0], {%1,%2,%3,%4};"
                :: "r"(base + PAR), "r"(s0), "r"(s1), "r"(s2), "r"(s3));
        }
        if constexpr (KK >= 71 && (KK & 15) == 7) {
            pstep<((KK + 8) >> 6) - 1, ((KK + 8) >> 4) & 3>(CTX_ARGS);
        }
        if constexpr (KK >= 79 && (KK & 15) == 15) {
            mstep(CTX_ARGS);
        }
        if constexpr ((KK & 63) == 63) { __syncwarp(); }
    }
}

// ---- ascending-k traversal (validated in R13/R14/R16) ----
template <int... Is>
__device__ __forceinline__ void do_deg1(ISeq<Is...>, CTX_DECL) {
    (emitk<1 + Is>(xs[Is], CTX_ARGS), ...);
}
template <int P>
__device__ __forceinline__ void do_p2(CTX_DECL) {
    constexpr int A = pair_a(P);
    constexpr int B = P - A * (A + 1) / 2;
    emitk<17 + P>(xs[A] * xs[B], CTX_ARGS);
}
template <int... Ps>
__device__ __forceinline__ void do_deg2(ISeq<Ps...>, CTX_DECL) {
    (do_p2<Ps>(CTX_ARGS), ...);
}
template <int II, int A, int... Bs>
__device__ __forceinline__ void emit3run(float tp, ISeq<Bs...>, CTX_DECL) {
    (emitk<ROW3(II, A, Bs)>(tp * xs[Bs], CTX_ARGS), ...);
}
template <int II, int... As>
__device__ __forceinline__ void do_ii(ISeq<As...>, CTX_DECL) {
    (emit3run<II, As>(xs[II] * xs[As], typename MkSeq<As + 1>::T{}, CTX_ARGS), ...);
}
template <int... IIs>
__device__ __forceinline__ void do_deg3(ISeq<IIs...>, CTX_DECL) {
    (do_ii<IIs>(typename MkSeq<IIs + 1>::T{}, CTX_ARGS), ...);
}
template <int... Js>
__device__ __forceinline__ void do_pad(ISeq<Js...>, CTX_DECL) {
    (emitk<969 + Js>(0.0f, CTX_ARGS), ...);
}

__global__ void __launch_bounds__(BLOCK, 2)
taylor_mma(const float* __restrict__ x, const float* __restrict__ W,
           float* __restrict__ out)
{
    extern __shared__ unsigned char smem[];
    const u32 sbase = smem_u32(smem);
    const int tid = threadIdx.x;
    const int warp = tid >> 5;
    const int lane = tid & 31;
    const int g = lane >> 2;          // fragment row group 0..7
    const int t = lane & 3;           // thread-in-group 0..3

    // ---- build B fragments once (validated R7/R8/R13/R14/R16) ----
#pragma unroll 1
    for (int e = tid; e < NSTEP * 32; e += BLOCK) {
        int s = e >> 5, l = e & 31;
        int lg = l >> 2, lt = l & 3;
        int k1 = 16 * s + 2 * lt;
#define WGET(K, C) (((K) < 969) ? W[(K) * NF + (C)] : 0.0f)
        uint4 v;
        v.x = packf16(WGET(k1 + 1, lg),     WGET(k1, lg));
        v.y = packf16(WGET(k1 + 9, lg),     WGET(k1 + 8, lg));
        v.z = packf16(WGET(k1 + 1, lg + 8), WGET(k1, lg + 8));
        v.w = packf16(WGET(k1 + 9, lg + 8), WGET(k1 + 8, lg + 8));
#undef WGET
        *reinterpret_cast<uint4*>(smem + e * 16) = v;
    }
    __syncthreads();

    // ---- stage addressing (row-major, unit swizzle phys=(u^(row&7))*16) ----
    const u32 stg = sbase + PSM_OFF + warp * PSM_PER_WARP;   // buf0; buf1=+4096
    const u32 l7 = (u32)(lane & 7);
    const u32 rowb = stg + (u32)lane * 128;
    const u32 sa0 = rowb + ((0u ^ l7) << 4);
    const u32 sa1 = rowb + ((1u ^ l7) << 4);
    const u32 sa2 = rowb + ((2u ^ l7) << 4);
    const u32 sa3 = rowb + ((3u ^ l7) << 4);
    const u32 sa4 = rowb + ((4u ^ l7) << 4);
    const u32 sa5 = rowb + ((5u ^ l7) << 4);
    const u32 sa6 = rowb + ((6u ^ l7) << 4);
    const u32 sa7 = rowb + ((7u ^ l7) << 4);
    const u32 rsu0 = stg + (u32)(lane & 15) * 128;
    const u32 rsu1 = rsu0 + 2048;
    const u32 lu = (u32)(lane >> 4);
    const u32 x0 = ((0u + lu) ^ l7) << 4;
    const u32 x1 = ((2u + lu) ^ l7) << 4;
    const u32 x2 = ((4u + lu) ^ l7) << 4;
    const u32 x3 = ((6u + lu) ^ l7) << 4;
    const u32 rb = sbase + lane * 16;    // B fragment base

    // ---- ticket software pipeline ----
    u32 tk;
    if (lane == 0) tk = atomicAdd(&g_ticket, 1u);
    tk = __shfl_sync(0xffffffffu, tk, 0);

    while (tk < NTILES) {
        const long long base = (long long)tk * 32;

        const float4* xv = reinterpret_cast<const float4*>(x + (base + lane) * NF);
        float4 v0 = xv[0], v1 = xv[1], v2 = xv[2], v3 = xv[3];

        // prefetch next ticket NOW (lane 0); shfl deferred past the epilogue
        u32 tknext_l0 = 0;
        if (lane == 0) tknext_l0 = atomicAdd(&g_ticket, 1u);

        float xs[NF] = { v0.x, v0.y, v0.z, v0.w,  v1.x, v1.y, v1.z, v1.w,
                         v2.x, v2.y, v2.z, v2.w,  v3.x, v3.y, v3.z, v3.w };

        float d00 = 0, d01 = 0, d02 = 0, d03 = 0;   // su0,nt0
        float d10 = 0, d11 = 0, d12 = 0, d13 = 0;   // su0,nt1
        float d20 = 0, d21 = 0, d22 = 0, d23 = 0;   // su1,nt0
        float d30 = 0, d31 = 0, d32 = 0, d33 = 0;   // su1,nt1
        float pend = 0.0f;
        u32 s0 = 0, s1 = 0, s2 = 0, s3 = 0;
        u32 pa0 = 0, pa1 = 0, pa2 = 0, pa3 = 0;
        u32 pc0 = 0, pc1 = 0, pc2 = 0, pc3 = 0;
        u32 pb0 = 0, pb1 = 0, pb2 = 0, pb3 = 0;

        // ---- fully-expanded generation, ascending k = 0..975 ----
        emitk<0>(1.0f, CTX_ARGS);
        do_deg1(typename MkSeq<16>::T{}, CTX_ARGS);
        do_deg2(typename MkSeq<136>::T{}, CTX_ARGS);
        do_deg3(typename MkSeq<16>::T{}, CTX_ARGS);
        do_pad(typename MkSeq<KTOT - 969>::T{}, CTX_ARGS);

        // tail: chunk 15 STS (KK 961..975) not followed by a chunk-boundary
        // syncwarp -> order explicitly before reading kstep (15,0).
        __syncwarp();
        pstep<14, 1>(CTX_ARGS); mstep(CTX_ARGS);
        pstep<14, 2>(CTX_ARGS); mstep(CTX_ARGS);
        pstep<14, 3>(CTX_ARGS); mstep(CTX_ARGS);
        pstep<15, 0>(CTX_ARGS); mstep(CTX_ARGS);

        // ---- epilogue: out = x + D (f32; x path exact) ----
#define EPI(D0, D1, D2, D3, SU, NT) do {                                       \
        long long rlo = base + (SU) * 16 + g;                                  \
        int c = (NT) * 8 + 2 * t;                                              \
        const float2 xlo = *reinterpret_cast<const float2*>(x + rlo * NF + c); \
        float2 olo; olo.x = xlo.x + (D0); olo.y = xlo.y + (D1);                \
        *reinterpret_cast<float2*>(out + rlo * NF + c) = olo;                  \
        const float2 xhi = *reinterpret_cast<const float2*>(x + (rlo + 8) * NF + c); \
        float2 ohi; ohi.x = xhi.x + (D2); ohi.y = xhi.y + (D3);                \
        *reinterpret_cast<float2*>(out + (rlo + 8) * NF + c) = ohi;            \
    } while (0)
        EPI(d00, d01, d02, d03, 0, 0);
        EPI(d10, d11, d12, d13, 0, 1);
        EPI(d20, d21, d22, d23, 1, 0);
        EPI(d30, d31, d32, d33, 1, 1);
#undef EPI

        tk = __shfl_sync(0xffffffffu, tknext_l0, 0);
    }
}

extern "C" void kernel_launch(void* const* d_in, const int* in_sizes, int n_in,
                              void* d_out, int out_size)
{
    const float* x = (const float*)d_in[0];   // [262144, 16]
    const float* W = (const float*)d_in[1];   // [969, 16]
    float* out = (float*)d_out;

    cudaFuncSetAttribute(taylor_mma,
                         cudaFuncAttributeMaxDynamicSharedMemorySize,
                         SMEM_TOTAL);

    reset_ticket_kernel<<<1, 1>>>();
    taylor_mma<<<GRID, BLOCK, SMEM_TOTAL>>>(x, W, out);
}